// round 1
// baseline (speedup 1.0000x reference)
#include <cuda_runtime.h>
#include <math.h>

// ---------------------------------------------------------------------------
// GraphConvolution (hyperbolic GCN layer), fp32.
// Pipeline:
//   1. k_hb:    hyp_bias = proj(expmap0(bias, c), c)                  [64]
//   2. k_xnorm: per-row ||x||                                         [N]
//   3. k_gemm:  mx = x @ W                                            [N,64]
//   4. k_epi:   mobius_matvec scaling + mobius_add(hb) + logmap0      [N,64]
//   5. k_zero:  clear accumulator
//   6. k_spmm:  accum[row] += vals * tmp[col]   (float4 vector RED)
//   7. k_final: out = proj(expmap0(accum, c), c)                      [N,64]
// ---------------------------------------------------------------------------

#define MAXN  50432
#define FOUT  64        // OUT dimension (fixed by problem shape)
#define MIN_NORM 1e-15f
#define BALL_EPS 4e-3f

__device__ float g_hb[FOUT];
__device__ float g_xn[MAXN];
__device__ float g_mx[MAXN * FOUT];
__device__ float g_tmp[MAXN * FOUT];
__device__ float g_accum[MAXN * FOUT];

__device__ __forceinline__ float warp_sum(float v) {
    #pragma unroll
    for (int o = 16; o > 0; o >>= 1) v += __shfl_xor_sync(0xffffffffu, v, o);
    return v;
}

__device__ __forceinline__ float artanh_clamped(float v) {
    v = fminf(fmaxf(v, -1.0f + 1e-7f), 1.0f - 1e-7f);
    return 0.5f * (log1pf(v) - log1pf(-v));
}

// --- 1. hyperbolic bias: proj(expmap0(bias)) ; single warp ------------------
__global__ void k_hb(const float* __restrict__ bias, const float* __restrict__ cp) {
    int lane = threadIdx.x;
    float c = cp[0];
    float sc = sqrtf(c);
    float u0 = bias[lane], u1 = bias[lane + 32];
    float s = warp_sum(u0 * u0 + u1 * u1);
    float un = fmaxf(sqrtf(s), MIN_NORM);
    float scale = tanhf(sc * un) / (sc * un);
    float p0 = scale * u0, p1 = scale * u1;
    float pn = fmaxf(sqrtf(warp_sum(p0 * p0 + p1 * p1)), MIN_NORM);
    float maxn = (1.0f - BALL_EPS) / sc;
    float f = (pn > maxn) ? (maxn / pn) : 1.0f;
    g_hb[lane] = p0 * f;
    g_hb[lane + 32] = p1 * f;
}

// --- 2. per-row ||x|| ; one warp per row ------------------------------------
__global__ void k_xnorm(const float* __restrict__ X, int N, int IN) {
    int warp = (blockIdx.x * blockDim.x + threadIdx.x) >> 5;
    int lane = threadIdx.x & 31;
    if (warp >= N) return;
    const float4* xr = reinterpret_cast<const float4*>(X + (size_t)warp * IN);
    int n4 = IN >> 2;
    float s = 0.f;
    for (int k = lane; k < n4; k += 32) {
        float4 v = xr[k];
        s += v.x * v.x + v.y * v.y + v.z * v.z + v.w * v.w;
    }
    s = warp_sum(s);
    if (lane == 0) g_xn[warp] = fmaxf(sqrtf(s), MIN_NORM);
}

// --- 3. SGEMM: mx[N,64] = X[N,IN] @ W[IN,64] --------------------------------
#define BM 64
#define BN 64
#define BK 32
__global__ void k_gemm(const float* __restrict__ X, const float* __restrict__ W,
                       int N, int IN) {
    __shared__ float As[BK][BM + 4];
    __shared__ float Bs[BK][BN];
    int tid = threadIdx.x;              // 256 threads
    int block_row = blockIdx.x * BM;
    int tx = tid & 15;                  // 16 col groups (4 cols each)
    int ty = tid >> 4;                  // 16 row groups (4 rows each)
    float acc[4][4] = {};

    for (int k0 = 0; k0 < IN; k0 += BK) {
        #pragma unroll
        for (int i = 0; i < (BM * BK) / 256; i++) {
            int idx = tid + i * 256;
            int r = idx >> 5;           // row within tile
            int cc = idx & 31;          // k within tile
            int gr = block_row + r;
            float v = (gr < N) ? X[(size_t)gr * IN + k0 + cc] : 0.f;
            As[cc][r] = v;
        }
        #pragma unroll
        for (int i = 0; i < (BK * BN) / 256; i++) {
            int idx = tid + i * 256;
            int r = idx >> 6;
            int cc = idx & 63;
            Bs[r][cc] = W[(size_t)(k0 + r) * BN + cc];
        }
        __syncthreads();
        #pragma unroll
        for (int k = 0; k < BK; k++) {
            float a[4], b[4];
            #pragma unroll
            for (int i = 0; i < 4; i++) a[i] = As[k][ty * 4 + i];
            #pragma unroll
            for (int j = 0; j < 4; j++) b[j] = Bs[k][tx * 4 + j];
            #pragma unroll
            for (int i = 0; i < 4; i++)
                #pragma unroll
                for (int j = 0; j < 4; j++)
                    acc[i][j] += a[i] * b[j];
        }
        __syncthreads();
    }
    #pragma unroll
    for (int i = 0; i < 4; i++) {
        int gr = block_row + ty * 4 + i;
        if (gr < N) {
            #pragma unroll
            for (int j = 0; j < 4; j++)
                g_mx[(size_t)gr * BN + tx * 4 + j] = acc[i][j];
        }
    }
}

// --- 4. epilogue: mobius_matvec scale, mobius_add(hb), logmap0 --------------
// one warp per row; lane handles columns lane and lane+32 (OUT == 64)
__global__ void k_epi(const float* __restrict__ cp, int N) {
    int warp = (blockIdx.x * blockDim.x + threadIdx.x) >> 5;
    int lane = threadIdx.x & 31;
    if (warp >= N) return;
    float c = cp[0];
    float sc = sqrtf(c);

    size_t base = (size_t)warp * FOUT;
    float mx0 = g_mx[base + lane];
    float mx1 = g_mx[base + lane + 32];
    float s = warp_sum(mx0 * mx0 + mx1 * mx1);
    bool allzero = (s == 0.0f);
    float mxn = fmaxf(sqrtf(s), MIN_NORM);
    float x_n = g_xn[warp];

    float at = artanh_clamped(sc * x_n);
    float scl = tanhf(mxn / x_n * at) / (mxn * sc);
    if (allzero) scl = 0.0f;
    float r0 = scl * mx0, r1 = scl * mx1;

    float h0 = g_hb[lane], h1 = g_hb[lane + 32];
    float x2 = warp_sum(r0 * r0 + r1 * r1);
    float y2 = warp_sum(h0 * h0 + h1 * h1);
    float xy = warp_sum(r0 * h0 + r1 * h1);

    float A = 1.0f + 2.0f * c * xy + c * y2;
    float B = 1.0f - c * x2;
    float den = fmaxf(1.0f + 2.0f * c * xy + c * c * x2 * y2, MIN_NORM);
    float a0 = (A * r0 + B * h0) / den;
    float a1 = (A * r1 + B * h1) / den;

    float pn = fmaxf(sqrtf(warp_sum(a0 * a0 + a1 * a1)), MIN_NORM);
    float at2 = artanh_clamped(sc * pn);
    float t = at2 / (sc * pn);
    g_tmp[base + lane]      = t * a0;
    g_tmp[base + lane + 32] = t * a1;
}

// --- 5. zero accumulator -----------------------------------------------------
__global__ void k_zero(int n4) {
    int i = blockIdx.x * blockDim.x + threadIdx.x;
    if (i < n4) reinterpret_cast<float4*>(g_accum)[i] = make_float4(0.f, 0.f, 0.f, 0.f);
}

// --- 6. SpMM: accum[row[e]] += vals[e] * tmp[col[e]] --------------------------
// half-warp (16 lanes) per edge; each lane owns one float4 chunk of the 64 cols
__global__ void k_spmm(const float* __restrict__ vals, const int* __restrict__ row,
                       const int* __restrict__ col, int E) {
    int g = blockIdx.x * blockDim.x + threadIdx.x;
    int e = g >> 4;
    int lane = g & 15;
    if (e >= E) return;
    int cc = col[e];
    int rr = row[e];
    float v = vals[e];
    const float4* src = reinterpret_cast<const float4*>(g_tmp + (size_t)cc * FOUT);
    float4 t = src[lane];
    float4 a = make_float4(t.x * v, t.y * v, t.z * v, t.w * v);
    atomicAdd(reinterpret_cast<float4*>(g_accum + (size_t)rr * FOUT) + lane, a);
}

// --- 7. final: out = proj(expmap0(accum)) ------------------------------------
__global__ void k_final(const float* __restrict__ cp, float* __restrict__ out, int N) {
    int warp = (blockIdx.x * blockDim.x + threadIdx.x) >> 5;
    int lane = threadIdx.x & 31;
    if (warp >= N) return;
    float c = cp[0];
    float sc = sqrtf(c);
    size_t base = (size_t)warp * FOUT;
    float u0 = g_accum[base + lane];
    float u1 = g_accum[base + lane + 32];
    float un = fmaxf(sqrtf(warp_sum(u0 * u0 + u1 * u1)), MIN_NORM);
    float scale = tanhf(sc * un) / (sc * un);
    float p0 = scale * u0, p1 = scale * u1;
    float pn = fmaxf(sqrtf(warp_sum(p0 * p0 + p1 * p1)), MIN_NORM);
    float maxn = (1.0f - BALL_EPS) / sc;
    float f = (pn > maxn) ? (maxn / pn) : 1.0f;
    out[base + lane]      = p0 * f;
    out[base + lane + 32] = p1 * f;
}

// ---------------------------------------------------------------------------

extern "C" void kernel_launch(void* const* d_in, const int* in_sizes, int n_in,
                              void* d_out, int out_size) {
    const float* x    = (const float*)d_in[0];
    const float* w    = (const float*)d_in[1];
    const float* bias = (const float*)d_in[2];
    const float* vals = (const float*)d_in[3];
    const float* c    = (const float*)d_in[4];
    const int*   row  = (const int*)d_in[5];
    const int*   col  = (const int*)d_in[6];
    float* out = (float*)d_out;

    int OUT = in_sizes[2];               // 64
    int IN  = in_sizes[1] / OUT;         // 256
    int N   = in_sizes[0] / IN;          // 50000
    int E   = in_sizes[3];               // 800000
    (void)OUT; (void)n_in; (void)out_size;

    // 1. hyperbolic bias
    k_hb<<<1, 32>>>(bias, c);

    // 2. per-row x norms (warp per row)
    int rowBlocks = (N + 7) / 8;   // 8 warps / 256-thread block
    k_xnorm<<<rowBlocks, 256>>>(x, N, IN);

    // 3. SGEMM
    k_gemm<<<(N + BM - 1) / BM, 256>>>(x, w, N, IN);

    // 4. epilogue
    k_epi<<<rowBlocks, 256>>>(c, N);

    // 5. zero accumulator
    int n4 = (N * FOUT) / 4;
    k_zero<<<(n4 + 255) / 256, 256>>>(n4);

    // 6. SpMM scatter-add
    long long tot = (long long)E * 16;
    k_spmm<<<(int)((tot + 255) / 256), 256>>>(vals, row, col, E);

    // 7. final expmap0 + proj
    k_final<<<rowBlocks, 256>>>(c, out, N);
}

// round 2
// speedup vs baseline: 1.1470x; 1.1470x over previous
#include <cuda_runtime.h>
#include <math.h>

// ---------------------------------------------------------------------------
// GraphConvolution (hyperbolic GCN layer), fp32 — fused pipeline:
//   1. k_gemm_fused: mx = x@W, per-row ||x|| (free during load), hyp_bias
//      (warp 0 per block), mobius_matvec scale + mobius_add + logmap0 in
//      registers, zero accumulator rows             -> g_tmp, g_accum=0
//   2. k_spmm:  accum[row] += vals * tmp[col]   (float4 vector RED)
//   3. k_final: out = proj(expmap0(accum, c), c)
// ---------------------------------------------------------------------------

#define MAXN  50432
#define FOUT  64
#define MIN_NORM 1e-15f
#define BALL_EPS 4e-3f

__device__ float g_tmp[MAXN * FOUT];
__device__ float g_accum[MAXN * FOUT];

__device__ __forceinline__ float warp_sum(float v) {
    #pragma unroll
    for (int o = 16; o > 0; o >>= 1) v += __shfl_xor_sync(0xffffffffu, v, o);
    return v;
}
// reduce within each 16-lane half of a warp
__device__ __forceinline__ float red16(float v) {
    #pragma unroll
    for (int o = 8; o > 0; o >>= 1) v += __shfl_xor_sync(0xffffffffu, v, o);
    return v;
}

__device__ __forceinline__ float artanh_clamped(float v) {
    v = fminf(fmaxf(v, -1.0f + 1e-7f), 1.0f - 1e-7f);
    return 0.5f * (log1pf(v) - log1pf(-v));
}

// --- 1. fused GEMM + all row-wise epilogues ---------------------------------
#define BM 64
#define BN 64
#define BK 32
__global__ void __launch_bounds__(256, 2)
k_gemm_fused(const float* __restrict__ X, const float* __restrict__ W,
             const float* __restrict__ bias, const float* __restrict__ cp,
             int N, int IN) {
    __shared__ float As[BK][BM + 4];
    __shared__ float Bs[BK][BN];
    __shared__ float s_xn[BM];
    __shared__ float s_hb[FOUT];
    __shared__ float s_y2;

    int tid  = threadIdx.x;             // 256 threads
    int lane = tid & 31;
    int wrp  = tid >> 5;                // 0..7
    int block_row = blockIdx.x * BM;
    int tx = tid & 15;                  // 16 col groups (4 cols each)
    int ty = tid >> 4;                  // 16 row groups (4 rows each)

    float c  = cp[0];
    float sc = sqrtf(c);

    // warp 0: hyperbolic bias  hb = proj(expmap0(bias, c), c), plus ||hb||^2
    if (wrp == 0) {
        float u0 = bias[lane], u1 = bias[lane + 32];
        float un = fmaxf(sqrtf(warp_sum(u0 * u0 + u1 * u1)), MIN_NORM);
        float scale = tanhf(sc * un) / (sc * un);
        float p0 = scale * u0, p1 = scale * u1;
        float pn2 = warp_sum(p0 * p0 + p1 * p1);
        float pn = fmaxf(sqrtf(pn2), MIN_NORM);
        float maxn = (1.0f - BALL_EPS) / sc;
        float f = (pn > maxn) ? (maxn / pn) : 1.0f;
        s_hb[lane]      = p0 * f;
        s_hb[lane + 32] = p1 * f;
        if (lane == 0) {
            float hn = fminf(pn, maxn);
            s_y2 = hn * hn;
        }
    }

    float acc[4][4] = {};
    float xsum[8] = {};   // partial ||x||^2 per covered row

    for (int k0 = 0; k0 < IN; k0 += BK) {
        #pragma unroll
        for (int i = 0; i < (BM * BK) / 256; i++) {      // 8 iters
            int idx = tid + i * 256;
            int r  = idx >> 5;          // = wrp + 8*i
            int cc = idx & 31;
            int gr = block_row + r;
            float v = (gr < N) ? X[(size_t)gr * IN + k0 + cc] : 0.f;
            As[cc][r] = v;
            xsum[i] += v * v;
        }
        #pragma unroll
        for (int i = 0; i < (BK * BN) / 256; i++) {
            int idx = tid + i * 256;
            int r  = idx >> 6;
            int cc = idx & 63;
            Bs[r][cc] = W[(size_t)(k0 + r) * BN + cc];
        }
        __syncthreads();
        #pragma unroll
        for (int k = 0; k < BK; k++) {
            float a[4], b[4];
            #pragma unroll
            for (int i = 0; i < 4; i++) a[i] = As[k][ty * 4 + i];
            #pragma unroll
            for (int j = 0; j < 4; j++) b[j] = Bs[k][tx * 4 + j];
            #pragma unroll
            for (int i = 0; i < 4; i++)
                #pragma unroll
                for (int j = 0; j < 4; j++)
                    acc[i][j] += a[i] * b[j];
        }
        __syncthreads();
    }

    // per-row x norms: warp w owns rows {w + 8i}
    #pragma unroll
    for (int i = 0; i < 8; i++) {
        float s = warp_sum(xsum[i]);
        if (lane == 0) s_xn[wrp + 8 * i] = fmaxf(sqrtf(s), MIN_NORM);
    }

    // zero accumulator rows for this block (overlaps with reduction latency)
    {
        float4 z = make_float4(0.f, 0.f, 0.f, 0.f);
        float4* ab = reinterpret_cast<float4*>(g_accum + (size_t)block_row * FOUT);
        int n4 = BM * FOUT / 4;         // 1024
        int lim4 = ((N - block_row) < BM ? (N - block_row) : BM) * FOUT / 4;
        #pragma unroll
        for (int i = 0; i < n4 / 256; i++) {
            int idx = tid + i * 256;
            if (idx < lim4) ab[idx] = z;
        }
    }
    __syncthreads();

    float y2 = s_y2;
    float h[4];
    #pragma unroll
    for (int j = 0; j < 4; j++) h[j] = s_hb[tx * 4 + j];

    // epilogue: 4 rows per thread; each row's 64 cols live in 16 lanes
    #pragma unroll
    for (int i = 0; i < 4; i++) {
        int row = block_row + ty * 4 + i;

        float smx = 0.f, sxh = 0.f;
        #pragma unroll
        for (int j = 0; j < 4; j++) {
            smx += acc[i][j] * acc[i][j];
            sxh += acc[i][j] * h[j];
        }
        smx = red16(smx);                    // ||mx||^2
        sxh = red16(sxh);                    // mx . hb

        float x_n = s_xn[ty * 4 + i];
        float mxn = fmaxf(sqrtf(smx), MIN_NORM);
        float at  = artanh_clamped(sc * x_n);
        float scl = tanhf(mxn / x_n * at) / (mxn * sc);
        if (smx == 0.0f) scl = 0.0f;

        float x2 = scl * scl * smx;          // ||r||^2
        float xy = scl * sxh;                // r . hb

        float A = 1.0f + 2.0f * c * xy + c * y2;
        float B = 1.0f - c * x2;
        float den = fmaxf(1.0f + 2.0f * c * xy + c * c * x2 * y2, MIN_NORM);
        float inv_den = 1.0f / den;

        float a0[4], pa = 0.f;
        #pragma unroll
        for (int j = 0; j < 4; j++) {
            a0[j] = (A * (scl * acc[i][j]) + B * h[j]) * inv_den;
            pa += a0[j] * a0[j];
        }
        pa = red16(pa);
        float pn = fmaxf(sqrtf(pa), MIN_NORM);
        float t = artanh_clamped(sc * pn) / (sc * pn);

        if (row < N) {
            float4 o = make_float4(t * a0[0], t * a0[1], t * a0[2], t * a0[3]);
            *reinterpret_cast<float4*>(g_tmp + (size_t)row * FOUT + tx * 4) = o;
        }
    }
}

// --- 2. SpMM: accum[row[e]] += vals[e] * tmp[col[e]] --------------------------
__global__ void k_spmm(const float* __restrict__ vals, const int* __restrict__ row,
                       const int* __restrict__ col, int E) {
    int g = blockIdx.x * blockDim.x + threadIdx.x;
    int e = g >> 4;
    int lane = g & 15;
    if (e >= E) return;
    int cc = __ldg(col + e);
    int rr = __ldg(row + e);
    float v = __ldg(vals + e);
    float4 t = *reinterpret_cast<const float4*>(g_tmp + (size_t)cc * FOUT + lane * 4);
    float4 a = make_float4(t.x * v, t.y * v, t.z * v, t.w * v);
    atomicAdd(reinterpret_cast<float4*>(g_accum + (size_t)rr * FOUT) + lane, a);
}

// --- 3. final: out = proj(expmap0(accum)) ------------------------------------
__global__ void k_final(const float* __restrict__ cp, float* __restrict__ out, int N) {
    int warp = (blockIdx.x * blockDim.x + threadIdx.x) >> 5;
    int lane = threadIdx.x & 31;
    if (warp >= N) return;
    float c = cp[0];
    float sc = sqrtf(c);
    size_t base = (size_t)warp * FOUT;
    float u0 = g_accum[base + lane];
    float u1 = g_accum[base + lane + 32];
    float un = fmaxf(sqrtf(warp_sum(u0 * u0 + u1 * u1)), MIN_NORM);
    float scale = tanhf(sc * un) / (sc * un);
    float p0 = scale * u0, p1 = scale * u1;
    float pn = fmaxf(sqrtf(warp_sum(p0 * p0 + p1 * p1)), MIN_NORM);
    float maxn = (1.0f - BALL_EPS) / sc;
    float f = (pn > maxn) ? (maxn / pn) : 1.0f;
    out[base + lane]      = p0 * f;
    out[base + lane + 32] = p1 * f;
}

// ---------------------------------------------------------------------------

extern "C" void kernel_launch(void* const* d_in, const int* in_sizes, int n_in,
                              void* d_out, int out_size) {
    const float* x    = (const float*)d_in[0];
    const float* w    = (const float*)d_in[1];
    const float* bias = (const float*)d_in[2];
    const float* vals = (const float*)d_in[3];
    const float* c    = (const float*)d_in[4];
    const int*   row  = (const int*)d_in[5];
    const int*   col  = (const int*)d_in[6];
    float* out = (float*)d_out;

    int OUT = in_sizes[2];               // 64
    int IN  = in_sizes[1] / OUT;         // 256
    int N   = in_sizes[0] / IN;          // 50000
    int E   = in_sizes[3];               // 800000
    (void)OUT; (void)n_in; (void)out_size;

    // 1. fused GEMM + epilogues (+ accumulator zeroing)
    k_gemm_fused<<<(N + BM - 1) / BM, 256>>>(x, w, bias, c, N, IN);

    // 2. SpMM scatter-add
    long long tot = (long long)E * 16;
    k_spmm<<<(int)((tot + 255) / 256), 256>>>(vals, row, col, E);

    // 3. final expmap0 + proj
    int rowBlocks = (N + 7) / 8;
    k_final<<<rowBlocks, 256>>>(c, out, N);
}